// round 10
// baseline (speedup 1.0000x reference)
#include <cuda_runtime.h>
#include <cstdint>

#define BS 4096
#define D  100
#define H  16
#define P  2

#define BPB 8
#define THREADS 256
#define GRID (BS / BPB)          // 512
#define UNITS (D * BPB)          // 800 units: (t, c)

// ---- device scratch (allocation-free rule) ----
// W0C[(g*100+t)*16 + i] = float4{ W0[t,i,4g..4g+3] }
__device__ float4 g_W0C[25 * D * H];   // 640 KB

__device__ __forceinline__ float leaky1(float v) { return fmaxf(v, 0.01f * v); }

// ---------------- prep: W0 -> g-major float4 ----------------
__global__ void prep_kernel(const float* __restrict__ W0)
{
    int n = blockIdx.x * blockDim.x + threadIdx.x;
    if (n < 25 * D * H) {
        int g = n / (D * H);
        int r = n - g * (D * H);
        int t = r >> 4;
        int i = r & 15;
        g_W0C[n] = *(const float4*)(W0 + (size_t)(t * H + i) * D + 4 * g);
    }
}

// ---------------- main: thread = (t, c); no shuffles, no mainloop syncs ----------------
__global__ __launch_bounds__(THREADS, 4)
void basemodel_kernel(const float* __restrict__ x,
                      const float* __restrict__ log_alpha,
                      const float* __restrict__ noise,
                      const float* __restrict__ b0,
                      const float* __restrict__ W1,
                      const float* __restrict__ b1,
                      const float* __restrict__ W2,
                      const float* __restrict__ b2,
                      float* __restrict__ out)
{
    __shared__ unsigned char s_mask[D * D];        // 10 KB: [(j>>2)*100+t)*4 + (j&3)]
    __shared__ __align__(16) float s_x[BPB][104];  // 3.3 KB, 104-pad: LDS.128 conflict-free

    const int tid = threadIdx.x;
    const int b0i = blockIdx.x * BPB;

    // ---- stage x[c][j] ----
    for (int m = tid; m < BPB * D; m += THREADS) {
        int c = m / D, j = m - c * D;
        s_x[c][j] = x[(size_t)(b0i + c) * D + j];
    }

    // ---- Phase A: Gumbel-hard mask bytes, fully linear in m = j*100 + t ----
    // ST-estimator forward value == y_hard: keep iff (log_alpha+noise) > 0 and j != t.
    {
        const float* nz = noise + (size_t)b0i * D * D;
        for (int m = tid; m < D * D; m += THREADS) {
            int j = m / D;
            int t = m - j * D;
            float la = log_alpha[m];
            unsigned bits = 0;
            #pragma unroll
            for (int c = 0; c < 8; ++c)
                bits |= ((la + nz[(size_t)c * D * D + m]) > 0.0f) ? (1u << c) : 0u;
            if (j == t) bits = 0;
            s_mask[((j >> 2) * D + t) * 4 + (j & 3)] = (unsigned char)bits;
        }
    }
    __syncthreads();

    // ---- units: u = t*8 + c; 800 over 4 passes (pass 3 = warp 0 exactly) ----
    #pragma unroll 1
    for (int k = 0; k < 4; ++k) {
        const int u = k * THREADS + tid;
        if (u >= UNITS) continue;                  // whole warp skips together
        const int t = u >> 3;
        const int c = u & 7;

        // ---- Phase B: layer0 -> h1[16] in regs ----
        float h1[16];
        #pragma unroll
        for (int i = 0; i < 16; ++i) h1[i] = 0.0f;

        const float4* w0p = g_W0C + (size_t)t * 16;
        const unsigned* mrow = (const unsigned*)s_mask + t;   // word (g*100+t) at [g*25... ] careful
        #pragma unroll 5
        for (int g = 0; g < 25; ++g) {
            unsigned mw = ((const unsigned*)s_mask)[g * D + t];   // 4 mask bytes (jj=0..3)
            float4 xv  = *(const float4*)(s_x[c] + 4 * g);
            unsigned mc = mw >> c;                 // bit 8*jj = mask bit for this c
            float xm0 = (mc & 0x1u)       ? xv.x : 0.0f;
            float xm1 = (mc & 0x100u)     ? xv.y : 0.0f;
            float xm2 = (mc & 0x10000u)   ? xv.z : 0.0f;
            float xm3 = (mc & 0x1000000u) ? xv.w : 0.0f;
            const float4* wg = w0p + (size_t)g * (D * 16);
            #pragma unroll
            for (int i = 0; i < 16; ++i) {
                float4 w = wg[i];                  // broadcast across 8 c-lanes
                h1[i] = fmaf(w.x, xm0, h1[i]);
                h1[i] = fmaf(w.y, xm1, h1[i]);
                h1[i] = fmaf(w.z, xm2, h1[i]);
                h1[i] = fmaf(w.w, xm3, h1[i]);
            }
        }
        {
            const float4* bp = (const float4*)(b0 + (size_t)t * 16);
            #pragma unroll
            for (int q = 0; q < 4; ++q) {
                float4 bv = bp[q];
                h1[4 * q + 0] = leaky1(h1[4 * q + 0] + bv.x);
                h1[4 * q + 1] = leaky1(h1[4 * q + 1] + bv.y);
                h1[4 * q + 2] = leaky1(h1[4 * q + 2] + bv.z);
                h1[4 * q + 3] = leaky1(h1[4 * q + 3] + bv.w);
            }
        }

        // ---- Phase C: layer1, thread-local; W1 native rows (broadcast loads) ----
        float h2[16];
        const float4* w1p = (const float4*)(W1 + (size_t)t * H * H);
        #pragma unroll
        for (int i2 = 0; i2 < 16; ++i2) {
            float4 wa = w1p[i2 * 4 + 0];
            float4 wb = w1p[i2 * 4 + 1];
            float4 wc = w1p[i2 * 4 + 2];
            float4 wd = w1p[i2 * 4 + 3];
            float acc;
            acc = wa.x * h1[0];
            acc = fmaf(wa.y, h1[1], acc);  acc = fmaf(wa.z, h1[2], acc);
            acc = fmaf(wa.w, h1[3], acc);  acc = fmaf(wb.x, h1[4], acc);
            acc = fmaf(wb.y, h1[5], acc);  acc = fmaf(wb.z, h1[6], acc);
            acc = fmaf(wb.w, h1[7], acc);  acc = fmaf(wc.x, h1[8], acc);
            acc = fmaf(wc.y, h1[9], acc);  acc = fmaf(wc.z, h1[10], acc);
            acc = fmaf(wc.w, h1[11], acc); acc = fmaf(wd.x, h1[12], acc);
            acc = fmaf(wd.y, h1[13], acc); acc = fmaf(wd.z, h1[14], acc);
            acc = fmaf(wd.w, h1[15], acc);
            h2[i2] = acc;
        }
        {
            const float4* bp = (const float4*)(b1 + (size_t)t * 16);
            #pragma unroll
            for (int q = 0; q < 4; ++q) {
                float4 bv = bp[q];
                h2[4 * q + 0] = leaky1(h2[4 * q + 0] + bv.x);
                h2[4 * q + 1] = leaky1(h2[4 * q + 1] + bv.y);
                h2[4 * q + 2] = leaky1(h2[4 * q + 2] + bv.z);
                h2[4 * q + 3] = leaky1(h2[4 * q + 3] + bv.w);
            }
        }

        // ---- Phase D: output layer, thread-local, direct coalesced-ish store ----
        const float4* w2p = (const float4*)(W2 + (size_t)t * P * H);
        float p0 = 0.0f, p1 = 0.0f;
        #pragma unroll
        for (int q = 0; q < 4; ++q) {
            float4 wa = w2p[q];                    // W2[t,0,4q..]
            float4 wb = w2p[4 + q];                // W2[t,1,4q..]
            p0 = fmaf(wa.x, h2[4 * q + 0], p0); p0 = fmaf(wa.y, h2[4 * q + 1], p0);
            p0 = fmaf(wa.z, h2[4 * q + 2], p0); p0 = fmaf(wa.w, h2[4 * q + 3], p0);
            p1 = fmaf(wb.x, h2[4 * q + 0], p1); p1 = fmaf(wb.y, h2[4 * q + 1], p1);
            p1 = fmaf(wb.z, h2[4 * q + 2], p1); p1 = fmaf(wb.w, h2[4 * q + 3], p1);
        }
        float2 bb = *(const float2*)(b2 + (size_t)t * P);
        *(float2*)(out + (size_t)(b0i + c) * D * P + (size_t)t * P) =
            make_float2(p0 + bb.x, p1 + bb.y);
    }
}

extern "C" void kernel_launch(void* const* d_in, const int* in_sizes, int n_in,
                              void* d_out, int out_size)
{
    const float* x         = (const float*)d_in[0];
    const float* log_alpha = (const float*)d_in[1];
    const float* noise     = (const float*)d_in[2];
    const float* W0        = (const float*)d_in[3];
    const float* b0        = (const float*)d_in[4];
    const float* W1        = (const float*)d_in[5];
    const float* b1        = (const float*)d_in[6];
    const float* W2        = (const float*)d_in[7];
    const float* b2        = (const float*)d_in[8];
    float* out             = (float*)d_out;

    prep_kernel<<<(25 * D * H + 255) / 256, 256>>>(W0);

    basemodel_kernel<<<GRID, THREADS>>>(
        x, log_alpha, noise, b0, W1, b1, W2, b2, out);
}